// round 5
// baseline (speedup 1.0000x reference)
#include <cuda_runtime.h>
#include <cuda_fp16.h>

#define D        128
#define TILE_R   128
#define NTHREADS 256
#define PSTRIDE  132   // padded row stride (floats): 33 x 16B (odd) -> conflict-free float4 rows
#define USTRIDE  132

// Shared (floats):
//   sPiN [128*PSTRIDE] : sPiN[c][k] = Pi[c][k]   (natural; GEMM1 reads rows over k)
//   sPiT [128*PSTRIDE] : sPiT[c][k] = Pi[k][c]   (transposed; GEMM2 reads rows over k)
//   sUV  [TILE_R*USTRIDE] : normalized u, then (after GEMM1) quantized v
//   sNorm[TILE_R], sCen[16]
#define SMEM_FLOATS (2*128*PSTRIDE + TILE_R*USTRIDE + TILE_R + 16)

// Packed fp32x2 FMA: acc(2xf32) += a(2xf32) * b(2xf32), element-wise, full fp32.
#define FMA2(acc, a, b) \
    asm("fma.rn.f32x2 %0, %1, %2, %0;" : "+l"(acc) : "l"(a), "l"(b))

__device__ __forceinline__ float hadd2(unsigned long long a) {
    float lo = __uint_as_float((unsigned)(a & 0xffffffffull));
    float hi = __uint_as_float((unsigned)(a >> 32));
    return lo + hi;
}

__global__ __launch_bounds__(NTHREADS, 1)
void tq_kernel(const float* __restrict__ x, const float* __restrict__ Pi,
               const float* __restrict__ cen, const float* __restrict__ bnd,
               float* __restrict__ out, int nrows, int ntiles)
{
    extern __shared__ float sm[];
    float* sPiN  = sm;
    float* sPiT  = sPiN + 128 * PSTRIDE;
    float* sUV   = sPiT + 128 * PSTRIDE;
    float* sNorm = sUV  + TILE_R * USTRIDE;
    float* sCen  = sNorm + TILE_R;

    const int tid = threadIdx.x;

    // Stage Pi in both layouts (once; block is persistent).
    for (int idx = tid; idx < D * D; idx += NTHREADS) {
        int j = idx >> 7;        // Pi row
        int k = idx & (D - 1);   // Pi col
        float p = Pi[idx];
        sPiN[j * PSTRIDE + k] = p;   // natural
        sPiT[k * PSTRIDE + j] = p;   // transposed
    }
    if (tid < 16) sCen[tid] = cen[tid];

    float b[15];
    #pragma unroll
    for (int i = 0; i < 15; i++) b[i] = bnd[i + 1];

    const int cg = tid & 31;   // 4 cols: cg*4 .. cg*4+3 (lane id -> coalesced/conflict-free)
    const int rg = tid >> 5;   // 16 rows: rg*16 .. rg*16+15 (warp-uniform -> u broadcasts)

    __syncthreads();

    for (int tile = blockIdx.x; tile < ntiles; tile += gridDim.x) {
        const int row0 = tile * TILE_R;

        // ---- Phase 1: load x, per-row norm, write normalized u ----
        {
            int lrow = tid >> 1;       // 0..127
            int sub  = tid & 1;        // 2 threads/row, 16 float4 each
            int grow = row0 + lrow;
            const float4* xp = (const float4*)(x + (size_t)grow * D) + sub * 16;
            float4 v[16];
            float ss = 0.f;
            #pragma unroll
            for (int i = 0; i < 16; i++) {
                float4 t = (grow < nrows) ? xp[i] : make_float4(0.f, 0.f, 0.f, 0.f);
                v[i] = t;
                ss += t.x * t.x + t.y * t.y + t.z * t.z + t.w * t.w;
            }
            ss += __shfl_xor_sync(0xffffffffu, ss, 1);
            float norm = sqrtf(ss);
            float inv  = 1.0f / (norm + 1e-8f);
            float4* up = (float4*)(sUV + lrow * USTRIDE) + sub * 16;
            #pragma unroll
            for (int i = 0; i < 16; i++) {
                float4 t = v[i];
                t.x *= inv; t.y *= inv; t.z *= inv; t.w *= inv;
                up[i] = t;
            }
            if (sub == 0)
                sNorm[lrow] = __half2float(__float2half_rn(norm));
        }
        __syncthreads();

        // ---- GEMM1: rotated[r][c] = sum_k u[r][k] * Pi[c][k]  (f32x2 over k) ----
        unsigned long long acc[16][4];
        #pragma unroll
        for (int r = 0; r < 16; r++)
            #pragma unroll
            for (int j = 0; j < 4; j++) acc[r][j] = 0ull;

        #pragma unroll 2
        for (int k = 0; k < D; k += 4) {
            ulonglong2 p0 = *(const ulonglong2*)&sPiN[(cg * 4 + 0) * PSTRIDE + k];
            ulonglong2 p1 = *(const ulonglong2*)&sPiN[(cg * 4 + 1) * PSTRIDE + k];
            ulonglong2 p2 = *(const ulonglong2*)&sPiN[(cg * 4 + 2) * PSTRIDE + k];
            ulonglong2 p3 = *(const ulonglong2*)&sPiN[(cg * 4 + 3) * PSTRIDE + k];
            #pragma unroll
            for (int r = 0; r < 16; r++) {
                ulonglong2 u = *(const ulonglong2*)&sUV[(rg * 16 + r) * USTRIDE + k];
                FMA2(acc[r][0], u.x, p0.x); FMA2(acc[r][0], u.y, p0.y);
                FMA2(acc[r][1], u.x, p1.x); FMA2(acc[r][1], u.y, p1.y);
                FMA2(acc[r][2], u.x, p2.x); FMA2(acc[r][2], u.y, p2.y);
                FMA2(acc[r][3], u.x, p3.x); FMA2(acc[r][3], u.y, p3.y);
            }
        }
        __syncthreads();   // all GEMM1 reads of sUV done before v overwrites it

        // ---- Bucketize (count(b < x)) + codebook gather; write v into sUV ----
        #pragma unroll
        for (int r = 0; r < 16; r++) {
            float4 vv;
            #pragma unroll
            for (int c = 0; c < 4; c++) {
                float xv = hadd2(acc[r][c]);
                int idx = 0;
                #pragma unroll
                for (int i = 0; i < 15; i++) idx += (xv > b[i]) ? 1 : 0;
                ((float*)&vv)[c] = sCen[idx];
            }
            *(float4*)&sUV[(rg * 16 + r) * USTRIDE + cg * 4] = vv;
        }
        __syncthreads();

        // ---- GEMM2: recon[r][c] = sum_k v[r][k] * Pi[k][c]  (f32x2 over k) ----
        #pragma unroll
        for (int r = 0; r < 16; r++)
            #pragma unroll
            for (int j = 0; j < 4; j++) acc[r][j] = 0ull;

        #pragma unroll 2
        for (int k = 0; k < D; k += 4) {
            ulonglong2 p0 = *(const ulonglong2*)&sPiT[(cg * 4 + 0) * PSTRIDE + k];
            ulonglong2 p1 = *(const ulonglong2*)&sPiT[(cg * 4 + 1) * PSTRIDE + k];
            ulonglong2 p2 = *(const ulonglong2*)&sPiT[(cg * 4 + 2) * PSTRIDE + k];
            ulonglong2 p3 = *(const ulonglong2*)&sPiT[(cg * 4 + 3) * PSTRIDE + k];
            #pragma unroll
            for (int r = 0; r < 16; r++) {
                ulonglong2 v = *(const ulonglong2*)&sUV[(rg * 16 + r) * USTRIDE + k];
                FMA2(acc[r][0], v.x, p0.x); FMA2(acc[r][0], v.y, p0.y);
                FMA2(acc[r][1], v.x, p1.x); FMA2(acc[r][1], v.y, p1.y);
                FMA2(acc[r][2], v.x, p2.x); FMA2(acc[r][2], v.y, p2.y);
                FMA2(acc[r][3], v.x, p3.x); FMA2(acc[r][3], v.y, p3.y);
            }
        }

        // ---- Epilogue: rescale by fp16-roundtripped norm, coalesced float4 store ----
        #pragma unroll
        for (int r = 0; r < 16; r++) {
            int grow = row0 + rg * 16 + r;
            if (grow < nrows) {
                float nq = sNorm[rg * 16 + r];
                float4 o;
                o.x = hadd2(acc[r][0]) * nq;
                o.y = hadd2(acc[r][1]) * nq;
                o.z = hadd2(acc[r][2]) * nq;
                o.w = hadd2(acc[r][3]) * nq;
                *(float4*)(out + (size_t)grow * D + cg * 4) = o;
            }
        }
        __syncthreads();   // protect sUV/sNorm before next tile's phase 1
    }
}

extern "C" void kernel_launch(void* const* d_in, const int* in_sizes, int n_in,
                              void* d_out, int out_size)
{
    const float* x   = (const float*)d_in[0];
    const float* Pi  = (const float*)d_in[1];
    const float* cen = (const float*)d_in[2];
    const float* bnd = (const float*)d_in[3];
    float* out = (float*)d_out;

    int nrows  = in_sizes[0] / D;
    int ntiles = (nrows + TILE_R - 1) / TILE_R;

    size_t smem = (size_t)SMEM_FLOATS * sizeof(float);
    cudaFuncSetAttribute(tq_kernel, cudaFuncAttributeMaxDynamicSharedMemorySize,
                         (int)smem);

    int dev = 0;
    cudaGetDevice(&dev);
    int nsm = 148;
    cudaDeviceGetAttribute(&nsm, cudaDevAttrMultiProcessorCount, dev);
    int grid = ntiles < nsm ? ntiles : nsm;

    tq_kernel<<<grid, NTHREADS, smem>>>(x, Pi, cen, bnd, out, nrows, ntiles);
}